// round 1
// baseline (speedup 1.0000x reference)
#include <cuda_runtime.h>
#include <cstdint>

// Fixed problem shapes (registry problem is fixed-shape; runtime values checked vs these maxima)
#define N_MAX 50000
#define E_MAX 800000
#define B_MAX 1024

// ---------------- device scratch (no allocations allowed) ----------------
__device__ float    g_agg [N_MAX * 64];
__device__ float    g_cnt [N_MAX];
__device__ float    g_ya  [N_MAX * 64];
__device__ float    g_yb  [N_MAX * 64];
__device__ float    g_x0  [N_MAX * 6];
__device__ float    g_ea1 [(size_t)E_MAX * 64];
__device__ float    g_ea2 [(size_t)E_MAX * 64];
__device__ int      g_gcnt[B_MAX];
__device__ int      g_head[B_MAX];
__device__ unsigned g_pool[B_MAX * 64];

// ---------------- setup kernels ----------------
__global__ void k_gcnt(const int* __restrict__ batch, int N) {
    int i = blockIdx.x * 256 + threadIdx.x;
    if (i < N) atomicAdd(&g_gcnt[batch[i]], 1);
}

__global__ void k_ecnt(const int* __restrict__ col, const float* __restrict__ mask, int E) {
    int e = blockIdx.x * 256 + threadIdx.x;
    if (e < E) atomicAdd(&g_cnt[col[e]], mask[e]);
}

// exclusive prefix sum over graph counts -> head indices (single block, B<=1024)
__global__ void k_scan(int B) {
    __shared__ int s[1024];
    int t = threadIdx.x;
    int v = (t < B) ? g_gcnt[t] : 0;
    s[t] = v;
    __syncthreads();
    for (int off = 1; off < 1024; off <<= 1) {
        int add = (t >= off) ? s[t - off] : 0;
        __syncthreads();
        s[t] += add;
        __syncthreads();
    }
    if (t < B) g_head[t] = s[t] - v;   // exclusive
}

__global__ void k_x0set(const float* __restrict__ x, int B, int N) {
    int idx = blockIdx.x * 256 + threadIdx.x;
    if (idx >= B * 16) return;
    int b = idx >> 4, s = idx & 15;
    int n = (s < 8) ? g_head[b] : (g_head[b] + 1);
    int d = s & 7;
    if (d < 6 && n < N) g_x0[n * 6 + d] = x[n * 6 + d];
}

// ---------------- edge->node aggregation (vector atomics) ----------------
template <bool USE_EMB>
__global__ void k_scatter(const float* __restrict__ ea, const int* __restrict__ col,
                          const float* __restrict__ mask, const int* __restrict__ rel,
                          const float* __restrict__ emb, int E) {
    long idx = (long)blockIdx.x * 256 + threadIdx.x;
    if (idx >= (long)E * 4) return;
    int e = (int)(idx >> 2), q = (int)(idx & 3);
    float m = __ldg(&mask[e]);
    const float* src;
    if (USE_EMB) src = &emb[(size_t)__ldg(&rel[e]) * 64 + q * 16];
    else         src = &ea[(size_t)e * 64 + q * 16];
    float* dst = &g_agg[(size_t)__ldg(&col[e]) * 64 + q * 16];
#pragma unroll
    for (int i = 0; i < 4; i++) {
        float4 v = *(const float4*)(src + i * 4);
        v.x *= m; v.y *= m; v.z *= m; v.w *= m;
        atomicAdd((float4*)(dst + i * 4), v);   // red.global.add.v4.f32 (sm_90+)
    }
}

// ---------------- per-node GEMM: ya = W[:, :70]@nrx + b, yb = W[:,70:140]@nrx ----------------
#define NPB 8
__global__ void k_node(const float* __restrict__ W, const float* __restrict__ b, int N) {
    __shared__ float sW[128 * 70];       // rows 0..63: W[:, 0:70); rows 64..127: W[:, 70:140)
    __shared__ float snrx[NPB][72];
    int t = threadIdx.x;                 // 256 threads
    int nb = blockIdx.x * NPB;
    for (int i = t; i < 128 * 70; i += 256) {
        int r = i / 70, k = i % 70;
        sW[i] = (r < 64) ? W[r * 204 + k] : W[(r - 64) * 204 + 70 + k];
    }
    for (int i = t; i < NPB * 70; i += 256) {
        int ln = i / 70, k = i % 70;
        int n = nb + ln;
        float v = 0.f;
        if (n < N) {
            if (k < 64) v = g_agg[(size_t)n * 64 + k] / (g_cnt[n] + 1.0f);
            else        v = g_x0[(size_t)n * 6 + (k - 64)];
        }
        snrx[ln][k] = v;
    }
    __syncthreads();
    int o = t & 127;       // output row within [ya(64) | yb(64)]
    int half = t >> 7;     // node subgroup
    float acc[4] = {0.f, 0.f, 0.f, 0.f};
    const float* wrow = &sW[o * 70];
#pragma unroll 2
    for (int k = 0; k < 70; k++) {
        float w = wrow[k];
        acc[0] += w * snrx[half * 4 + 0][k];
        acc[1] += w * snrx[half * 4 + 1][k];
        acc[2] += w * snrx[half * 4 + 2][k];
        acc[3] += w * snrx[half * 4 + 3][k];
    }
    float bias = (o < 64) ? b[o] : 0.f;
#pragma unroll
    for (int j = 0; j < 4; j++) {
        int n = nb + half * 4 + j;
        if (n < N) {
            if (o < 64) g_ya[(size_t)n * 64 + o]        = acc[j] + bias;
            else        g_yb[(size_t)n * 64 + (o - 64)] = acc[j];
        }
    }
}

// ---------------- per-edge GEMM: out = relu(ya[row] + yb[col] + W[:,140:204]@ea) ----------------
// tile: 128 edges x 64 outs, 256 threads, thread tile 8 edges x 4 outs
#define EPB 128
#define SA_STRIDE 132
#define SW_STRIDE 68
#define EDGE_SMEM ((64 * SA_STRIDE + 64 * SW_STRIDE) * 4)

template <bool USE_EMB>
__global__ void k_edge(const float* __restrict__ ea_in, const float* __restrict__ W,
                       const int* __restrict__ row, const int* __restrict__ col,
                       const int* __restrict__ rel, const float* __restrict__ emb,
                       float* __restrict__ ea_out, int E) {
    extern __shared__ float smem[];
    float* sA = smem;                     // sA[k][e] : 64 x EPB, stride SA_STRIDE
    float* sW = smem + 64 * SA_STRIDE;    // sW[k][o] : 64 x 64,  stride SW_STRIDE
    int t = threadIdx.x;                  // 256
    long eb = (long)blockIdx.x * EPB;

    // load W_c transposed (k-major)
    for (int i = t; i < 64 * 64; i += 256) {
        int o = i >> 6, k = i & 63;
        sW[k * SW_STRIDE + o] = W[o * 204 + 140 + k];
    }
    // load ea tile transposed: coalesced float4 global reads
    for (int i = t; i < EPB * 16; i += 256) {
        int le = i >> 4, k4 = i & 15;
        long e = eb + le;
        float4 v = make_float4(0.f, 0.f, 0.f, 0.f);
        if (e < E) {
            if (USE_EMB) v = *(const float4*)(&emb[(size_t)__ldg(&rel[e]) * 64 + k4 * 4]);
            else         v = *(const float4*)(&ea_in[(size_t)e * 64 + k4 * 4]);
        }
        sA[(k4 * 4 + 0) * SA_STRIDE + le] = v.x;
        sA[(k4 * 4 + 1) * SA_STRIDE + le] = v.y;
        sA[(k4 * 4 + 2) * SA_STRIDE + le] = v.z;
        sA[(k4 * 4 + 3) * SA_STRIDE + le] = v.w;
    }
    __syncthreads();

    int te = t & 15;   // edge group: edges te*8 .. te*8+7
    int to = t >> 4;   // out  group: outs  to*4 .. to*4+3
    float acc[8][4];
#pragma unroll
    for (int i = 0; i < 8; i++)
#pragma unroll
        for (int j = 0; j < 4; j++) acc[i][j] = 0.f;

#pragma unroll 4
    for (int k = 0; k < 64; k++) {
        const float* aptr = &sA[k * SA_STRIDE + te * 8];
        float4 a0 = *(const float4*)(aptr);
        float4 a1 = *(const float4*)(aptr + 4);
        float4 w  = *(const float4*)(&sW[k * SW_STRIDE + to * 4]);
        float av[8] = {a0.x, a0.y, a0.z, a0.w, a1.x, a1.y, a1.z, a1.w};
        float wv[4] = {w.x, w.y, w.z, w.w};
#pragma unroll
        for (int i = 0; i < 8; i++)
#pragma unroll
            for (int j = 0; j < 4; j++) acc[i][j] += av[i] * wv[j];
    }

#pragma unroll
    for (int i = 0; i < 8; i++) {
        long e = eb + te * 8 + i;
        if (e < E) {
            int r = __ldg(&row[e]);
            int c = __ldg(&col[e]);
            float4 u = *(const float4*)(&g_ya[(size_t)r * 64 + to * 4]);
            float4 v = *(const float4*)(&g_yb[(size_t)c * 64 + to * 4]);
            float4 o;
            o.x = fmaxf(acc[i][0] + u.x + v.x, 0.f);
            o.y = fmaxf(acc[i][1] + u.y + v.y, 0.f);
            o.z = fmaxf(acc[i][2] + u.z + v.z, 0.f);
            o.w = fmaxf(acc[i][3] + u.w + v.w, 0.f);
            *(float4*)(&ea_out[(size_t)e * 64 + to * 4]) = o;
        }
    }
}

// ---------------- final node_rep + segment_max pooling ----------------
__global__ void k_final(const int* __restrict__ batch, float* __restrict__ node_rep, int N) {
    long idx = (long)blockIdx.x * 256 + threadIdx.x;
    if (idx >= (long)N * 64) return;
    int n = (int)(idx >> 6), d = (int)(idx & 63);
    float v = g_agg[idx] / (g_cnt[n] + 1.0f);
    node_rep[idx] = v;
    unsigned key = __float_as_uint(v);
    key = (key & 0x80000000u) ? ~key : (key | 0x80000000u);   // order-preserving map
    atomicMax(&g_pool[(size_t)batch[n] * 64 + d], key);
}

__global__ void k_graph(const float* __restrict__ node_rep, float* __restrict__ out_graph, int B) {
    int idx = blockIdx.x * 256 + threadIdx.x;
    if (idx >= B * 192) return;
    int b = idx / 192, j = idx % 192;
    float v;
    if (j < 64) {
        unsigned k = g_pool[(size_t)b * 64 + j];
        k = (k & 0x80000000u) ? (k & 0x7FFFFFFFu) : ~k;
        v = __uint_as_float(k);
    } else if (j < 128) {
        v = node_rep[(size_t)g_head[b] * 64 + (j - 64)];
    } else {
        v = node_rep[((size_t)g_head[b] + 1) * 64 + (j - 128)];
    }
    out_graph[idx] = v;
}

// ---------------- launch ----------------
extern "C" void kernel_launch(void* const* d_in, const int* in_sizes, int n_in,
                              void* d_out, int out_size) {
    const float* x     = (const float*)d_in[0];
    const int*   eidx  = (const int*)  d_in[1];
    const int*   erel  = (const int*)  d_in[2];
    const int*   batch = (const int*)  d_in[3];
    const float* mask  = (const float*)d_in[4];
    const float* emb   = (const float*)d_in[5];
    const float* Wl[3] = {(const float*)d_in[6], (const float*)d_in[8], (const float*)d_in[10]};
    const float* bl[3] = {(const float*)d_in[7], (const float*)d_in[9], (const float*)d_in[11]};

    int N = in_sizes[0] / 6;
    int E = in_sizes[2];
    int B = (int)(((long)out_size - 64L * (N + E)) / 192L);

    const int* row = eidx;
    const int* col = eidx + E;

    float* out       = (float*)d_out;
    float* out_graph = out;
    float* out_node  = out + (size_t)B * 192;
    float* out_ea    = out_node + (size_t)N * 64;

    void *p_agg, *p_cnt, *p_x0, *p_gcnt, *p_pool, *p_ea1, *p_ea2;
    cudaGetSymbolAddress(&p_agg,  g_agg);
    cudaGetSymbolAddress(&p_cnt,  g_cnt);
    cudaGetSymbolAddress(&p_x0,   g_x0);
    cudaGetSymbolAddress(&p_gcnt, g_gcnt);
    cudaGetSymbolAddress(&p_pool, g_pool);
    cudaGetSymbolAddress(&p_ea1,  g_ea1);
    cudaGetSymbolAddress(&p_ea2,  g_ea2);

    cudaFuncSetAttribute(k_edge<true>,  cudaFuncAttributeMaxDynamicSharedMemorySize, EDGE_SMEM);
    cudaFuncSetAttribute(k_edge<false>, cudaFuncAttributeMaxDynamicSharedMemorySize, EDGE_SMEM);

    // ---- setup ----
    cudaMemsetAsync(p_gcnt, 0, (size_t)B * sizeof(int));
    cudaMemsetAsync(p_cnt,  0, (size_t)N * sizeof(float));
    cudaMemsetAsync(p_x0,   0, (size_t)N * 6 * sizeof(float));
    k_gcnt<<<(N + 255) / 256, 256>>>(batch, N);
    k_ecnt<<<(E + 255) / 256, 256>>>(col, mask, E);
    k_scan<<<1, 1024>>>(B);
    k_x0set<<<(B * 16 + 255) / 256, 256>>>(x, B, N);

    int grid_sc   = (int)(((long)E * 4 + 255) / 256);
    int grid_node = (N + NPB - 1) / NPB;
    int grid_edge = (E + EPB - 1) / EPB;

    // ---- layer 0 (ea comes from edge_emb gather) ----
    cudaMemsetAsync(p_agg, 0, (size_t)N * 64 * sizeof(float));
    k_scatter<true><<<grid_sc, 256>>>(nullptr, col, mask, erel, emb, E);
    k_node<<<grid_node, 256>>>(Wl[0], bl[0], N);
    k_edge<true><<<grid_edge, 256, EDGE_SMEM>>>(nullptr, Wl[0], row, col, erel, emb,
                                                (float*)p_ea1, E);
    // ---- layer 1 ----
    cudaMemsetAsync(p_agg, 0, (size_t)N * 64 * sizeof(float));
    k_scatter<false><<<grid_sc, 256>>>((const float*)p_ea1, col, mask, nullptr, nullptr, E);
    k_node<<<grid_node, 256>>>(Wl[1], bl[1], N);
    k_edge<false><<<grid_edge, 256, EDGE_SMEM>>>((const float*)p_ea1, Wl[1], row, col, nullptr,
                                                 nullptr, (float*)p_ea2, E);
    // ---- layer 2 (writes final ea straight into d_out) ----
    cudaMemsetAsync(p_agg, 0, (size_t)N * 64 * sizeof(float));
    k_scatter<false><<<grid_sc, 256>>>((const float*)p_ea2, col, mask, nullptr, nullptr, E);
    k_node<<<grid_node, 256>>>(Wl[2], bl[2], N);
    k_edge<false><<<grid_edge, 256, EDGE_SMEM>>>((const float*)p_ea2, Wl[2], row, col, nullptr,
                                                 nullptr, out_ea, E);
    // ---- final aggregation + pooling ----
    cudaMemsetAsync(p_agg,  0, (size_t)N * 64 * sizeof(float));
    cudaMemsetAsync(p_pool, 0, (size_t)B * 64 * sizeof(unsigned));
    k_scatter<false><<<grid_sc, 256>>>(out_ea, col, mask, nullptr, nullptr, E);
    k_final<<<(int)(((long)N * 64 + 255) / 256), 256>>>(batch, out_node, N);
    k_graph<<<(B * 192 + 255) / 256, 256>>>(out_node, out_graph, B);
}